// round 1
// baseline (speedup 1.0000x reference)
#include <cuda_runtime.h>

typedef unsigned long long ull;

#define THREADS 128
#define SMEM_FLOATS 57344            // 3 quad arrays (3*4096*4) + 1 pair array (4096*2)
#define SMEM_BYTES  (SMEM_FLOATS * 4) // 229376 bytes

__device__ __forceinline__ ull pack2(float lo, float hi) {
    ull r; asm("mov.b64 %0, {%1, %2};" : "=l"(r) : "f"(lo), "f"(hi)); return r;
}
__device__ __forceinline__ void unpack2(ull v, float& lo, float& hi) {
    asm("mov.b64 {%0, %1}, %2;" : "=f"(lo), "=f"(hi) : "l"(v));
}
__device__ __forceinline__ ull mul2(ull a, ull b) {
    ull d; asm("mul.rn.f32x2 %0, %1, %2;" : "=l"(d) : "l"(a), "l"(b)); return d;
}
__device__ __forceinline__ ull fma2(ull a, ull b, ull c) {
    ull d; asm("fma.rn.f32x2 %0, %1, %2, %3;" : "=l"(d) : "l"(a), "l"(b), "l"(c)); return d;
}

// ANFIS: out[b] = (sum_r w[b,r] * f[b,r]) / (sum_r w[b,r] + 1e-8)
//   w[b,r]   = prod_i mu[b, i, digit_i(r)]   (digit 0 = most significant, base-4)
//   f[b,r]   = sum_j xa[b,j] * C[r,j],  xa = [x, 1]
// Restructured:
//   den[b]   = prod_i (sum_t mu[b,i,t])                (exact closed form)
//   G[b,j]   = sum_r w[b,r] * C[r,j]  (hierarchical partial products over digits)
//   out[b]   = (sum_j xa[b,j] * G[b,j]) / (den[b] + 1e-8)
// Each thread processes TWO batch elements packed into f32x2 register pairs.
__global__ void __launch_bounds__(THREADS, 1) anfis_kernel(
    const float* __restrict__ x,
    const float* __restrict__ centers,
    const float* __restrict__ sigmas,
    const float* __restrict__ cons,
    float* __restrict__ out,
    int half)
{
    extern __shared__ float sm[];
    // --- Build duplicated consequent table in SMEM ---
    // Layout (all offsets in floats):
    //   [0      , 16384) : Q0[r] = (c0,c0,c1,c1)   (ulonglong2, 16B aligned)
    //   [16384  , 32768) : Q1[r] = (c2,c2,c3,c3)
    //   [32768  , 49152) : Q2[r] = (c4,c4,c5,c5)
    //   [49152  , 57344) : P6[r] = (c6,c6)          (ull, 8B aligned)
    for (int idx = threadIdx.x; idx < 4096 * 7; idx += THREADS) {
        int r = idx / 7;
        int j = idx - r * 7;
        float v = cons[idx];
        float* dst;
        if (j < 6) dst = sm + ((j >> 1) << 14) + r * 4 + ((j & 1) << 1);
        else       dst = sm + 49152 + r * 2;
        dst[0] = v;
        dst[1] = v;
    }

    int g  = blockIdx.x * THREADS + threadIdx.x;
    int b0 = g;
    int b1 = g + half;

    // --- Load x rows and compute Gaussian memberships for both elements ---
    float xv0[6], xv1[6];
#pragma unroll
    for (int i = 0; i < 6; i++) { xv0[i] = x[b0 * 6 + i]; xv1[i] = x[b1 * 6 + i]; }

    ull lmu[12];                 // levels 0..2 (dynamic-indexed -> local mem, only 84 reads)
    ull rmu3[4], rmu4[4], rmu5[4]; // levels 3..5 (constant-indexed via full unroll -> registers)
    float den0 = 1.0f, den1 = 1.0f;
#pragma unroll
    for (int i = 0; i < 6; i++) {
        float s0 = 0.0f, s1 = 0.0f;
#pragma unroll
        for (int tt = 0; tt < 4; tt++) {
            float c   = centers[i * 4 + tt];
            float sg  = fabsf(sigmas[i * 4 + tt]) + 1e-6f;
            float inv = 0.5f / (sg * sg);
            float d0v = xv0[i] - c;
            float d1v = xv1[i] - c;
            float m0  = __expf(-d0v * d0v * inv);
            float m1  = __expf(-d1v * d1v * inv);
            s0 += m0; s1 += m1;
            ull mp = pack2(m0, m1);
            if (i < 3)       lmu[i * 4 + tt] = mp;
            else if (i == 3) rmu3[tt] = mp;
            else if (i == 4) rmu4[tt] = mp;
            else             rmu5[tt] = mp;
        }
        den0 *= s0; den1 *= s1;
    }
    __syncthreads();

    const ulonglong2* Q0 = (const ulonglong2*)(sm);
    const ulonglong2* Q1 = (const ulonglong2*)(sm + 16384);
    const ulonglong2* Q2 = (const ulonglong2*)(sm + 32768);
    const ull*        P6 = (const ull*)(sm + 49152);

    ull acc0 = 0, acc1 = 0, acc2 = 0, acc3 = 0, acc4 = 0, acc5 = 0, acc6 = 0;

    int rb = 0;
#pragma unroll 1
    for (int d0 = 0; d0 < 4; d0++) {
        ull A0 = lmu[d0];
#pragma unroll 1
        for (int d1 = 0; d1 < 4; d1++) {
            ull A1 = mul2(A0, lmu[4 + d1]);
#pragma unroll 1
            for (int d2 = 0; d2 < 4; d2++) {
                ull A2 = mul2(A1, lmu[8 + d2]);
#pragma unroll
                for (int d3 = 0; d3 < 4; d3++) {
                    ull A3 = mul2(A2, rmu3[d3]);
#pragma unroll
                    for (int d4 = 0; d4 < 4; d4++) {
                        ull A4 = mul2(A3, rmu4[d4]);
#pragma unroll
                        for (int d5 = 0; d5 < 4; d5++) {
                            int rr = rb + d3 * 16 + d4 * 4 + d5;
                            ull w = mul2(A4, rmu5[d5]);
                            ulonglong2 q0 = Q0[rr];
                            ulonglong2 q1 = Q1[rr];
                            ulonglong2 q2 = Q2[rr];
                            ull        p6 = P6[rr];
                            acc0 = fma2(w, q0.x, acc0);
                            acc1 = fma2(w, q0.y, acc1);
                            acc2 = fma2(w, q1.x, acc2);
                            acc3 = fma2(w, q1.y, acc3);
                            acc4 = fma2(w, q2.x, acc4);
                            acc5 = fma2(w, q2.y, acc5);
                            acc6 = fma2(w, p6, acc6);
                        }
                    }
                }
                rb += 64;
            }
        }
    }

    // --- Epilogue: num = xa . G ; out = num / (den + 1e-8) ---
    float g0[7], g1[7];
    unpack2(acc0, g0[0], g1[0]);
    unpack2(acc1, g0[1], g1[1]);
    unpack2(acc2, g0[2], g1[2]);
    unpack2(acc3, g0[3], g1[3]);
    unpack2(acc4, g0[4], g1[4]);
    unpack2(acc5, g0[5], g1[5]);
    unpack2(acc6, g0[6], g1[6]);

    float n0 = g0[6], n1 = g1[6];
#pragma unroll
    for (int i = 0; i < 6; i++) { n0 += g0[i] * xv0[i]; n1 += g1[i] * xv1[i]; }

    out[b0] = n0 / (den0 + 1e-8f);
    out[b1] = n1 / (den1 + 1e-8f);
}

extern "C" void kernel_launch(void* const* d_in, const int* in_sizes, int n_in,
                              void* d_out, int out_size) {
    const float* x       = (const float*)d_in[0];
    const float* centers = (const float*)d_in[1];
    const float* sigmas  = (const float*)d_in[2];
    const float* cons    = (const float*)d_in[3];
    float* out = (float*)d_out;

    int B    = in_sizes[0] / 6;   // 32768
    int half = B >> 1;            // 16384

    cudaFuncSetAttribute(anfis_kernel,
                         cudaFuncAttributeMaxDynamicSharedMemorySize, SMEM_BYTES);

    int blocks = half / THREADS;  // 128
    anfis_kernel<<<blocks, THREADS, SMEM_BYTES>>>(x, centers, sigmas, cons, out, half);
}

// round 2
// speedup vs baseline: 1.0903x; 1.0903x over previous
#include <cuda_runtime.h>

typedef unsigned long long ull;

#define THREADS 256
#define SMEM_FLOATS 57344            // 3 quad arrays (3*4096*4) + 1 pair array (4096*2)
#define SMEM_BYTES  (SMEM_FLOATS * 4) // 229376 bytes

__device__ __forceinline__ ull pack2(float lo, float hi) {
    ull r; asm("mov.b64 %0, {%1, %2};" : "=l"(r) : "f"(lo), "f"(hi)); return r;
}
__device__ __forceinline__ void unpack2(ull v, float& lo, float& hi) {
    asm("mov.b64 {%0, %1}, %2;" : "=f"(lo), "=f"(hi) : "l"(v));
}
__device__ __forceinline__ ull mul2(ull a, ull b) {
    ull d; asm("mul.rn.f32x2 %0, %1, %2;" : "=l"(d) : "l"(a), "l"(b)); return d;
}
__device__ __forceinline__ ull fma2(ull a, ull b, ull c) {
    ull d; asm("fma.rn.f32x2 %0, %1, %2, %3;" : "=l"(d) : "l"(a), "l"(b), "l"(c)); return d;
}

// ANFIS restructured:
//   den[b]   = prod_i (sum_t mu[b,i,t])
//   G[b,j]   = sum_r w[b,r] * C[r,j]  (hierarchical partial products, base-4 digits)
//   out[b]   = (sum_j xa[b,j] * G[b,j]) / (den[b] + 1e-8)
// Each thread: TWO batch elements packed in f32x2, HALF the rule space
// (d0 in {2h, 2h+1}, h = lane>>4). Warp-level shfl_xor(16) reduction at the end.
__global__ void __launch_bounds__(THREADS, 1) anfis_kernel(
    const float* __restrict__ x,
    const float* __restrict__ centers,
    const float* __restrict__ sigmas,
    const float* __restrict__ cons,
    float* __restrict__ out,
    int half)
{
    extern __shared__ float sm[];
    // --- Build duplicated consequent table in SMEM ---
    //   [0      , 16384) : Q0[r] = (c0,c0,c1,c1)   (ulonglong2, 16B aligned)
    //   [16384  , 32768) : Q1[r] = (c2,c2,c3,c3)
    //   [32768  , 49152) : Q2[r] = (c4,c4,c5,c5)
    //   [49152  , 57344) : P6[r] = (c6,c6)          (ull, 8B aligned)
    for (int idx = threadIdx.x; idx < 4096 * 7; idx += THREADS) {
        int r = idx / 7;
        int j = idx - r * 7;
        float v = cons[idx];
        float* dst;
        if (j < 6) dst = sm + ((j >> 1) << 14) + r * 4 + ((j & 1) << 1);
        else       dst = sm + 49152 + r * 2;
        dst[0] = v;
        dst[1] = v;
    }

    int lane  = threadIdx.x & 31;
    int warp  = threadIdx.x >> 5;
    int hsel  = lane >> 4;                               // 0 or 1: which d0 half
    int p     = blockIdx.x * 128 + warp * 16 + (lane & 15);  // batch pair id
    int b0 = p;
    int b1 = p + half;

    // --- Memberships for both elements (computed redundantly by both halves) ---
    float xv0[6], xv1[6];
#pragma unroll
    for (int i = 0; i < 6; i++) { xv0[i] = x[b0 * 6 + i]; xv1[i] = x[b1 * 6 + i]; }

    ull lmu[12];                   // levels 0..2 (dynamic-indexed)
    ull rmu3[4], rmu4[4], rmu5[4]; // levels 3..5 (register-resident via unroll)
    float den0 = 1.0f, den1 = 1.0f;
#pragma unroll
    for (int i = 0; i < 6; i++) {
        float s0 = 0.0f, s1 = 0.0f;
#pragma unroll
        for (int tt = 0; tt < 4; tt++) {
            float c   = centers[i * 4 + tt];
            float sg  = fabsf(sigmas[i * 4 + tt]) + 1e-6f;
            float inv = 0.5f / (sg * sg);
            float d0v = xv0[i] - c;
            float d1v = xv1[i] - c;
            float m0  = __expf(-d0v * d0v * inv);
            float m1  = __expf(-d1v * d1v * inv);
            s0 += m0; s1 += m1;
            ull mp = pack2(m0, m1);
            if (i < 3)       lmu[i * 4 + tt] = mp;
            else if (i == 3) rmu3[tt] = mp;
            else if (i == 4) rmu4[tt] = mp;
            else             rmu5[tt] = mp;
        }
        den0 *= s0; den1 *= s1;
    }
    __syncthreads();

    const ulonglong2* Q0 = (const ulonglong2*)(sm);
    const ulonglong2* Q1 = (const ulonglong2*)(sm + 16384);
    const ulonglong2* Q2 = (const ulonglong2*)(sm + 32768);
    const ull*        P6 = (const ull*)(sm + 49152);

    ull acc0 = 0, acc1 = 0, acc2 = 0, acc3 = 0, acc4 = 0, acc5 = 0, acc6 = 0;

    int d0_start = hsel * 2;
    int rb = d0_start * 1024;
#pragma unroll 1
    for (int d0 = d0_start; d0 < d0_start + 2; d0++) {
        ull A0 = lmu[d0];
#pragma unroll 1
        for (int d1 = 0; d1 < 4; d1++) {
            ull A1 = mul2(A0, lmu[4 + d1]);
#pragma unroll 1
            for (int d2 = 0; d2 < 4; d2++) {
                ull A2 = mul2(A1, lmu[8 + d2]);
#pragma unroll
                for (int d3 = 0; d3 < 4; d3++) {
                    ull A3 = mul2(A2, rmu3[d3]);
#pragma unroll
                    for (int d4 = 0; d4 < 4; d4++) {
                        ull A4 = mul2(A3, rmu4[d4]);
#pragma unroll
                        for (int d5 = 0; d5 < 4; d5++) {
                            int rr = rb + d3 * 16 + d4 * 4 + d5;
                            ull w = mul2(A4, rmu5[d5]);
                            ulonglong2 q0 = Q0[rr];
                            ulonglong2 q1 = Q1[rr];
                            ulonglong2 q2 = Q2[rr];
                            ull        p6 = P6[rr];
                            acc0 = fma2(w, q0.x, acc0);
                            acc1 = fma2(w, q0.y, acc1);
                            acc2 = fma2(w, q1.x, acc2);
                            acc3 = fma2(w, q1.y, acc3);
                            acc4 = fma2(w, q2.x, acc4);
                            acc5 = fma2(w, q2.y, acc5);
                            acc6 = fma2(w, p6, acc6);
                        }
                    }
                }
                rb += 64;
            }
        }
    }

    // --- Combine the two rule-halves within the warp (lane xor 16) ---
    unsigned mask = 0xFFFFFFFFu;
    acc0 += 0; // keep types simple; do float-wise adds after shuffle
    {
        float lo, hi, slo, shi;
        ull* accs[7] = { &acc0, &acc1, &acc2, &acc3, &acc4, &acc5, &acc6 };
#pragma unroll
        for (int j = 0; j < 7; j++) {
            unpack2(*accs[j], lo, hi);
            slo = __shfl_xor_sync(mask, lo, 16);
            shi = __shfl_xor_sync(mask, hi, 16);
            lo += slo; hi += shi;
            *accs[j] = pack2(lo, hi);
        }
    }

    // --- Epilogue: num = xa . G ; out = num / (den + 1e-8) ---
    if (hsel == 0) {
        float g0[7], g1[7];
        unpack2(acc0, g0[0], g1[0]);
        unpack2(acc1, g0[1], g1[1]);
        unpack2(acc2, g0[2], g1[2]);
        unpack2(acc3, g0[3], g1[3]);
        unpack2(acc4, g0[4], g1[4]);
        unpack2(acc5, g0[5], g1[5]);
        unpack2(acc6, g0[6], g1[6]);

        float n0 = g0[6], n1 = g1[6];
#pragma unroll
        for (int i = 0; i < 6; i++) { n0 += g0[i] * xv0[i]; n1 += g1[i] * xv1[i]; }

        out[b0] = n0 / (den0 + 1e-8f);
        out[b1] = n1 / (den1 + 1e-8f);
    }
}

extern "C" void kernel_launch(void* const* d_in, const int* in_sizes, int n_in,
                              void* d_out, int out_size) {
    const float* x       = (const float*)d_in[0];
    const float* centers = (const float*)d_in[1];
    const float* sigmas  = (const float*)d_in[2];
    const float* cons    = (const float*)d_in[3];
    float* out = (float*)d_out;

    int B    = in_sizes[0] / 6;   // 32768
    int half = B >> 1;            // 16384

    cudaFuncSetAttribute(anfis_kernel,
                         cudaFuncAttributeMaxDynamicSharedMemorySize, SMEM_BYTES);

    int blocks = 128;             // 128 pairs per block * 128 blocks = 16384 pairs
    anfis_kernel<<<blocks, THREADS, SMEM_BYTES>>>(x, centers, sigmas, cons, out, half);
}